// round 1
// baseline (speedup 1.0000x reference)
#include <cuda_runtime.h>
#include <math.h>

#define Bsz 64
#define Nn  16384
#define Mm  128
#define Cc  1024
#define EPSF 1e-16f

// ---------------- scratch (device globals; no allocs allowed) ----------------
__device__ float g_s[Bsz * Nn];          // beta * sim            (4 MB)
__device__ float g_w[Bsz * Nn];          // pre-sharpen weights   (4 MB)
__device__ float g_k[Bsz * Mm];          // key vectors
__device__ float g_prm[Bsz * 8];         // normk,beta,gate,gamma,s0,s1,s2
__device__ float g_part[Bsz * 32 * Mm];  // read partials         (1 MB)

// ---------------- helpers ----------------
__device__ __forceinline__ float softplusf(float x) {
    return fmaxf(x, 0.0f) + log1pf(expf(-fabsf(x)));
}
__device__ __forceinline__ float sigmoidf(float x) {
    return 1.0f / (1.0f + expf(-x));
}

// block reduce for 1024 threads (32 warps exactly)
__device__ __forceinline__ float blockReduceSum1024(float v) {
    __shared__ float sm[32];
    #pragma unroll
    for (int o = 16; o; o >>= 1) v += __shfl_xor_sync(0xffffffffu, v, o);
    int w = threadIdx.x >> 5, l = threadIdx.x & 31;
    if (l == 0) sm[w] = v;
    __syncthreads();
    if (w == 0) {
        v = sm[l];
        #pragma unroll
        for (int o = 16; o; o >>= 1) v += __shfl_xor_sync(0xffffffffu, v, o);
        if (l == 0) sm[0] = v;
    }
    __syncthreads();
    float r = sm[0];
    __syncthreads();
    return r;
}
__device__ __forceinline__ float blockReduceMax1024(float v) {
    __shared__ float sm[32];
    #pragma unroll
    for (int o = 16; o; o >>= 1) v = fmaxf(v, __shfl_xor_sync(0xffffffffu, v, o));
    int w = threadIdx.x >> 5, l = threadIdx.x & 31;
    if (l == 0) sm[w] = v;
    __syncthreads();
    if (w == 0) {
        v = sm[l];
        #pragma unroll
        for (int o = 16; o; o >>= 1) v = fmaxf(v, __shfl_xor_sync(0xffffffffu, v, o));
        if (l == 0) sm[0] = v;
    }
    __syncthreads();
    float r = sm[0];
    __syncthreads();
    return r;
}

// ---------------- kernel 1: projections ----------------
// one block per batch, 128 threads
__global__ void __launch_bounds__(128) proj_kernel(
    const float* __restrict__ ctrl,
    const float* __restrict__ key_w, const float* __restrict__ key_b,
    const float* __restrict__ beta_w, const float* __restrict__ beta_b,
    const float* __restrict__ gate_w, const float* __restrict__ gate_b,
    const float* __restrict__ shift_w, const float* __restrict__ shift_b,
    const float* __restrict__ gamma_w, const float* __restrict__ gamma_b)
{
    const int b = blockIdx.x, tid = threadIdx.x;
    __shared__ float sc[Cc];
    __shared__ float red[128];

    for (int i = tid; i < Cc; i += 128) sc[i] = ctrl[b * Cc + i];
    __syncthreads();

    // key projection: thread tid computes column tid
    float acc = 0.0f;
    #pragma unroll 8
    for (int c = 0; c < Cc; c++) acc = fmaf(sc[c], key_w[c * Mm + tid], acc);
    float kf = tanhf(acc + key_b[tid]);
    g_k[b * Mm + tid] = kf;

    // ||k||
    red[tid] = kf * kf;
    __syncthreads();
    #pragma unroll
    for (int s = 64; s; s >>= 1) { if (tid < s) red[tid] += red[tid + s]; __syncthreads(); }
    if (tid == 0) g_prm[b * 8 + 0] = sqrtf(red[0]);
    __syncthreads();

    // 6 small dots: beta, gate, gamma, shift0..2
    float p[6] = {0, 0, 0, 0, 0, 0};
    for (int c = tid; c < Cc; c += 128) {
        float v = sc[c];
        p[0] = fmaf(v, beta_w[c], p[0]);
        p[1] = fmaf(v, gate_w[c], p[1]);
        p[2] = fmaf(v, gamma_w[c], p[2]);
        p[3] = fmaf(v, shift_w[c * 3 + 0], p[3]);
        p[4] = fmaf(v, shift_w[c * 3 + 1], p[4]);
        p[5] = fmaf(v, shift_w[c * 3 + 2], p[5]);
    }
    __shared__ float dots[6];
    #pragma unroll
    for (int j = 0; j < 6; j++) {
        red[tid] = p[j];
        __syncthreads();
        #pragma unroll
        for (int s = 64; s; s >>= 1) { if (tid < s) red[tid] += red[tid + s]; __syncthreads(); }
        if (tid == 0) dots[j] = red[0];
        __syncthreads();
    }

    if (tid == 0) {
        float beta  = softplusf(dots[0] + beta_b[0]);
        float gate  = sigmoidf(dots[1] + gate_b[0]);
        float gamma = 1.0f + softplusf(dots[2] + gamma_b[0]);
        float l0 = dots[3] + shift_b[0];
        float l1 = dots[4] + shift_b[1];
        float l2 = dots[5] + shift_b[2];
        float mx = fmaxf(l0, fmaxf(l1, l2));
        float e0 = expf(l0 - mx), e1 = expf(l1 - mx), e2 = expf(l2 - mx);
        float inv = 1.0f / (e0 + e1 + e2);
        g_prm[b * 8 + 1] = beta;
        g_prm[b * 8 + 2] = gate;
        g_prm[b * 8 + 3] = gamma;
        g_prm[b * 8 + 4] = e0 * inv;
        g_prm[b * 8 + 5] = e1 * inv;
        g_prm[b * 8 + 6] = e2 * inv;
    }
}

// ---------------- kernel 2: content similarity (memory pass 1) ----------------
// one warp per memory row; float4 per lane = 512B row fully coalesced
__global__ void __launch_bounds__(256) sim_kernel(const float* __restrict__ mem)
{
    const int warp = (blockIdx.x * blockDim.x + threadIdx.x) >> 5;
    const int lane = threadIdx.x & 31;
    if (warp >= Bsz * Nn) return;
    const int b = warp >> 14;

    float4 m4 = __ldg(((const float4*)mem) + (size_t)warp * 32 + lane);
    float4 k4 = __ldg(((const float4*)g_k) + b * 32 + lane);

    float dot = m4.x * k4.x + m4.y * k4.y + m4.z * k4.z + m4.w * k4.w;
    float nrm = m4.x * m4.x + m4.y * m4.y + m4.z * m4.z + m4.w * m4.w;
    #pragma unroll
    for (int o = 16; o; o >>= 1) {
        dot += __shfl_xor_sync(0xffffffffu, dot, o);
        nrm += __shfl_xor_sync(0xffffffffu, nrm, o);
    }
    if (lane == 0) {
        float normk = g_prm[b * 8 + 0];
        float beta  = g_prm[b * 8 + 1];
        float sim = dot / (normk * sqrtf(nrm) + EPSF);
        g_s[warp] = beta * sim;
    }
}

// ---------------- kernel 3: softmax + gate + shift + sharpen ----------------
// one block per batch, 1024 threads, 16 elems/thread
__global__ void __launch_bounds__(1024) weights_kernel(
    const float* __restrict__ prev, float* __restrict__ out)
{
    const int b = blockIdx.x, tid = threadIdx.x;
    const float gate  = g_prm[b * 8 + 2];
    const float gamma = g_prm[b * 8 + 3];
    const float s0 = g_prm[b * 8 + 4];
    const float s1 = g_prm[b * 8 + 5];
    const float s2 = g_prm[b * 8 + 6];

    float sv[16];
    float mx = -3.4e38f;
    #pragma unroll
    for (int i = 0; i < 16; i++) {
        sv[i] = g_s[b * Nn + i * 1024 + tid];
        mx = fmaxf(mx, sv[i]);
    }
    mx = blockReduceMax1024(mx);

    float lsum = 0.0f;
    #pragma unroll
    for (int i = 0; i < 16; i++) { sv[i] = expf(sv[i] - mx); lsum += sv[i]; }
    float Z = blockReduceSum1024(lsum);

    const float gz = gate / Z;
    const float og = 1.0f - gate;
    #pragma unroll
    for (int i = 0; i < 16; i++) {
        int n = i * 1024 + tid;
        g_w[b * Nn + n] = sv[i] * gz + og * prev[b * Nn + n];
    }
    __syncthreads();

    float wp[16];
    float psum = 0.0f;
    #pragma unroll
    for (int i = 0; i < 16; i++) {
        int n = i * 1024 + tid;
        float wl = g_w[b * Nn + ((n - 1) & (Nn - 1))];
        float wc = g_w[b * Nn + n];
        float wr = g_w[b * Nn + ((n + 1) & (Nn - 1))];
        float w2 = s0 * wl + s1 * wc + s2 * wr;
        wp[i] = powf(w2, gamma);
        psum += wp[i];
    }
    float S = blockReduceSum1024(psum);
    float inv = 1.0f / (S + EPSF);
    #pragma unroll
    for (int i = 0; i < 16; i++)
        out[(size_t)b * Nn + i * 1024 + tid] = wp[i] * inv;
}

// ---------------- kernel 4: weighted read partials (memory pass 2) ----------------
// blockIdx = b*32 + chunk; each chunk covers 512 rows; warp-per-row, 8 warps
__global__ void __launch_bounds__(256) read_kernel(
    const float* __restrict__ mem, const float* __restrict__ wts)
{
    const int b = blockIdx.x >> 5;
    const int c = blockIdx.x & 31;
    const int wid = threadIdx.x >> 5, lane = threadIdx.x & 31;
    const int n0 = c * 512;

    float4 acc = make_float4(0.f, 0.f, 0.f, 0.f);
    for (int r = n0 + wid; r < n0 + 512; r += 8) {
        size_t row = (size_t)b * Nn + r;
        float wv = __ldg(wts + row);
        float4 m4 = __ldg(((const float4*)mem) + row * 32 + lane);
        acc.x = fmaf(wv, m4.x, acc.x);
        acc.y = fmaf(wv, m4.y, acc.y);
        acc.z = fmaf(wv, m4.z, acc.z);
        acc.w = fmaf(wv, m4.w, acc.w);
    }
    __shared__ float sm[8][Mm];
    sm[wid][lane * 4 + 0] = acc.x;
    sm[wid][lane * 4 + 1] = acc.y;
    sm[wid][lane * 4 + 2] = acc.z;
    sm[wid][lane * 4 + 3] = acc.w;
    __syncthreads();
    if (threadIdx.x < Mm) {
        float s = 0.0f;
        #pragma unroll
        for (int j = 0; j < 8; j++) s += sm[j][threadIdx.x];
        g_part[(size_t)blockIdx.x * Mm + threadIdx.x] = s;
    }
}

// ---------------- kernel 5: fold partials ----------------
__global__ void __launch_bounds__(256) reduce_kernel(float* __restrict__ out)
{
    int idx = blockIdx.x * blockDim.x + threadIdx.x;
    if (idx >= Bsz * Mm) return;
    int b = idx >> 7, m = idx & 127;
    float s = 0.0f;
    #pragma unroll
    for (int j = 0; j < 32; j++) s += g_part[((size_t)b * 32 + j) * Mm + m];
    out[(size_t)Bsz * Nn + idx] = s;
}

// ---------------- launch ----------------
extern "C" void kernel_launch(void* const* d_in, const int* in_sizes, int n_in,
                              void* d_out, int out_size)
{
    const float* ctrl    = (const float*)d_in[0];
    const float* prev    = (const float*)d_in[1];
    const float* mem     = (const float*)d_in[2];
    const float* key_w   = (const float*)d_in[3];
    const float* key_b   = (const float*)d_in[4];
    const float* beta_w  = (const float*)d_in[5];
    const float* beta_b  = (const float*)d_in[6];
    const float* gate_w  = (const float*)d_in[7];
    const float* gate_b  = (const float*)d_in[8];
    const float* shift_w = (const float*)d_in[9];
    const float* shift_b = (const float*)d_in[10];
    const float* gamma_w = (const float*)d_in[11];
    const float* gamma_b = (const float*)d_in[12];
    // d_in[13..16] = erase/add params: unused in read mode

    float* out = (float*)d_out;

    proj_kernel<<<Bsz, 128>>>(ctrl, key_w, key_b, beta_w, beta_b,
                              gate_w, gate_b, shift_w, shift_b, gamma_w, gamma_b);
    sim_kernel<<<(Bsz * Nn) / 8, 256>>>(mem);
    weights_kernel<<<Bsz, 1024>>>(prev, out);
    read_kernel<<<Bsz * 32, 256>>>(mem, out);
    reduce_kernel<<<(Bsz * Mm + 255) / 256, 256>>>(out);
}